// round 16
// baseline (speedup 1.0000x reference)
#include <cuda_runtime.h>
#include <cuda_bf16.h>
#include <math.h>
#include <stdint.h>

#define B_SZ    128
#define G_CNT   10000
#define KWID    20
#define C_OUT   3
#define LATD    2000
#define GC      30000
#define IN_LEN  200000
#define NSPLIT1 15

// scratch (__device__ globals; no allocations allowed)
__device__ float g_h[B_SZ * GC];                // encoder conv out (15.36 MB)
__device__ float g_part[NSPLIT1 * B_SZ * LATD]; // FC1 split-K partials (15.4 MB)
__device__ float g_z[B_SZ * LATD];              // latent
__device__ float g_d[B_SZ * GC];                // decoder FC out

__device__ __forceinline__ float lrelu(float x) { return x >= 0.0f ? x : 0.1f * x; }

// pack two floats into bf16x2: low half = lo (lower k index), high = hi
__device__ __forceinline__ uint32_t pack_bf16(float lo, float hi) {
    uint32_t r;
    asm("cvt.rn.bf16x2.f32 %0, %1, %2;" : "=r"(r) : "f"(hi), "f"(lo));
    return r;
}

__device__ __forceinline__ uint32_t smem_u32(const void* p) {
    uint32_t a;
    asm("{ .reg .u64 t; cvta.to.shared.u64 t, %1; cvt.u32.u64 %0, t; }" : "=r"(a) : "l"(p));
    return a;
}

__device__ __forceinline__ void ldsm4(uint32_t r[4], uint32_t addr) {
    asm volatile("ldmatrix.sync.aligned.m8n8.x4.shared.b16 {%0,%1,%2,%3}, [%4];"
                 : "=r"(r[0]), "=r"(r[1]), "=r"(r[2]), "=r"(r[3]) : "r"(addr));
}

__device__ __forceinline__ void mma_bf16(float c[4], const uint32_t a[4], const uint32_t b[2]) {
    asm volatile(
        "mma.sync.aligned.m16n8k16.row.col.f32.bf16.bf16.f32 "
        "{%0,%1,%2,%3}, {%4,%5,%6,%7}, {%8,%9}, {%0,%1,%2,%3};"
        : "+f"(c[0]), "+f"(c[1]), "+f"(c[2]), "+f"(c[3])
        : "r"(a[0]), "r"(a[1]), "r"(a[2]), "r"(a[3]), "r"(b[0]), "r"(b[1]));
}

// ---------------------------------------------------------------------------
// Kernel 1: grouped encoder conv  h[b,g,c] = lrelu(sum_k x[b,g*20+k]*w[g,c,k]+b)
// ---------------------------------------------------------------------------
__global__ __launch_bounds__(256) void enc_conv_k(
    const float* __restrict__ x, const float* __restrict__ w, const float* __restrict__ bias)
{
    int idx = blockIdx.x * blockDim.x + threadIdx.x;
    if (idx >= B_SZ * G_CNT) return;
    int b = idx / G_CNT, g = idx % G_CNT;

    const float4* xp = (const float4*)(x + (size_t)b * IN_LEN + g * KWID);
    float xv[20];
#pragma unroll
    for (int i = 0; i < 5; i++) {
        float4 t = xp[i];
        xv[4*i+0] = t.x; xv[4*i+1] = t.y; xv[4*i+2] = t.z; xv[4*i+3] = t.w;
    }
    const float* wp = w + (size_t)g * (C_OUT * KWID);
    float* hp = g_h + (size_t)b * GC + (size_t)g * C_OUT;
#pragma unroll
    for (int c = 0; c < C_OUT; c++) {
        const float4* wc = (const float4*)(wp + c * KWID);
        float acc = bias[g * C_OUT + c];
#pragma unroll
        for (int i = 0; i < 5; i++) {
            float4 t = wc[i];
            acc = fmaf(xv[4*i+0], t.x, acc);
            acc = fmaf(xv[4*i+1], t.y, acc);
            acc = fmaf(xv[4*i+2], t.z, acc);
            acc = fmaf(xv[4*i+3], t.w, acc);
        }
        hp[c] = lrelu(acc);
    }
}

// ---------------------------------------------------------------------------
// FC GEMM via bf16 mma.sync m16n8k16 + ldmatrix, register-staged pipeline.
// C[m,n] = sum_k A[m,k]*W[n,k]; A row-major [128,K], W row-major [N,K].
// Block tile 128x128, BK=32 floats. Combined smem tile: 128 rows x 128B
// (A bf16 in chunks 0-3, W bf16 in chunks 4-7), swizzle c^(r&7).
// Double-buffered; per iter: STS(prev-loaded regs) -> LDG(st+2) -> compute.
// LDG gets a full compute phase to land before its STS consumes it.
// fuse==0: raw partials -> g_part[(sp*128+m)*N+n]   (FC1)
// fuse==1: lrelu(acc+bias[n]) -> g_d                 (FC2)
// ---------------------------------------------------------------------------
extern __shared__ __align__(128) char smem_raw[];   // 2 stages x 16KB
#define SMEM_STAGE 16384
#define SMEM_BYTES 32768

__global__ __launch_bounds__(256, 2) void fc_bf16_k(
    int which, const float* __restrict__ W, const float* __restrict__ bias,
    int N, int K, int steps_total, int steps_per_split, int fuse)
{
    const float* __restrict__ A = which ? g_z : g_h;
    const int tid = threadIdx.x, warp = tid >> 5, lane = tid & 31;
    const int nbase = blockIdx.x * 128, sp = blockIdx.y;
    int s0 = sp * steps_per_split;
    int s1 = s0 + steps_per_split;
    if (s1 > steps_total) s1 = steps_total;

    const int wm = (warp >> 2) * 64;   // 0 or 64
    const int wn = (warp & 3) * 32;    // 0..96
    const int g = lane >> 2, tig = lane & 3;
    const uint32_t smb = smem_u32(smem_raw);

    float acc[4][4][4];
#pragma unroll
    for (int mt = 0; mt < 4; mt++)
#pragma unroll
        for (int nt = 0; nt < 4; nt++)
#pragma unroll
            for (int v = 0; v < 4; v++) acc[mt][nt][v] = 0.0f;

    // -------- register-staged loader --------
    const int lr = tid >> 1;     // row 0..127
    const int lh = tid & 1;      // k16 half within BK=32
    const int wrow = nbase + lr;
    float4 ra[4], rw[4];

    auto ldg_regs = [&](int st) {
        const int kf = st * 32 + lh * 16;
        const float4 z = make_float4(0.f, 0.f, 0.f, 0.f);
#pragma unroll
        for (int j = 0; j < 4; j++) {
            int k = kf + 4 * j;
            ra[j] = (k < K) ? *(const float4*)(A + (size_t)lr * K + k) : z;
        }
#pragma unroll
        for (int j = 0; j < 4; j++) {
            int k = kf + 4 * j;
            rw[j] = (wrow < N && k < K) ? *(const float4*)(W + (size_t)wrow * K + k) : z;
        }
    };
    auto sts_regs = [&](int buf) {
        char* base = smem_raw + buf * SMEM_STAGE + lr * 128;
        uint4 p0, p1, q0, q1;
        p0.x = pack_bf16(ra[0].x, ra[0].y); p0.y = pack_bf16(ra[0].z, ra[0].w);
        p0.z = pack_bf16(ra[1].x, ra[1].y); p0.w = pack_bf16(ra[1].z, ra[1].w);
        p1.x = pack_bf16(ra[2].x, ra[2].y); p1.y = pack_bf16(ra[2].z, ra[2].w);
        p1.z = pack_bf16(ra[3].x, ra[3].y); p1.w = pack_bf16(ra[3].z, ra[3].w);
        q0.x = pack_bf16(rw[0].x, rw[0].y); q0.y = pack_bf16(rw[0].z, rw[0].w);
        q0.z = pack_bf16(rw[1].x, rw[1].y); q0.w = pack_bf16(rw[1].z, rw[1].w);
        q1.x = pack_bf16(rw[2].x, rw[2].y); q1.y = pack_bf16(rw[2].z, rw[2].w);
        q1.z = pack_bf16(rw[3].x, rw[3].y); q1.w = pack_bf16(rw[3].z, rw[3].w);
        const int r7 = lr & 7;
        *(uint4*)(base + (((lh * 2 + 0) ^ r7) * 16)) = p0;
        *(uint4*)(base + (((lh * 2 + 1) ^ r7) * 16)) = p1;
        *(uint4*)(base + (((4 + lh * 2 + 0) ^ r7) * 16)) = q0;
        *(uint4*)(base + (((4 + lh * 2 + 1) ^ r7) * 16)) = q1;
    };

    // per-lane ldmatrix components
    const int a_lrow = (lane & 7) + ((lane >> 3) & 1) * 8;  // + wm + mt*16
    const int a_lk   = (lane >> 4) & 1;                      // k-half
    const int b_mi   = lane >> 3;                            // matrix idx 0..3
    const int b_lrow = lane & 7;                             // + wn + nt*8

    // prologue: fill buf0 with s0; preload s0+1 into regs
    ldg_regs(s0);
    sts_regs(0);
    ldg_regs(s0 + 1);
    __syncthreads();

    for (int st = s0; st < s1; ++st) {
        const int buf = (st - s0) & 1;
        if (st + 1 < s1) sts_regs(buf ^ 1);        // regs hold st+1 data (landed)
        if (st + 2 < s1) ldg_regs(st + 2);         // in flight during compute

        const uint32_t tbase = smb + buf * SMEM_STAGE;
#pragma unroll
        for (int kb = 0; kb < 2; kb++) {
            uint32_t af[4][4];
#pragma unroll
            for (int mt = 0; mt < 4; mt++) {
                int row = wm + mt * 16 + a_lrow;
                int ch  = 2 * kb + a_lk;
                ldsm4(af[mt], tbase + row * 128 + ((ch ^ (row & 7)) * 16));
            }
            uint32_t bf[4][2];
#pragma unroll
            for (int half = 0; half < 2; half++) {
                int nt  = half * 2 + (b_mi >> 1);
                int h   = b_mi & 1;
                int row = wn + nt * 8 + b_lrow;
                int ch  = 4 + 2 * kb + h;
                uint32_t t[4];
                ldsm4(t, tbase + row * 128 + ((ch ^ (row & 7)) * 16));
                bf[half * 2 + 0][0] = t[0]; bf[half * 2 + 0][1] = t[1];
                bf[half * 2 + 1][0] = t[2]; bf[half * 2 + 1][1] = t[3];
            }
#pragma unroll
            for (int mt = 0; mt < 4; mt++)
#pragma unroll
                for (int nt = 0; nt < 4; nt++)
                    mma_bf16(acc[mt][nt], af[mt], bf[nt]);
        }
        __syncthreads();
    }

    // -------- epilogue --------
#pragma unroll
    for (int mt = 0; mt < 4; mt++) {
        int m0 = wm + mt * 16 + g;
#pragma unroll
        for (int nt = 0; nt < 4; nt++) {
            int n = nbase + wn + nt * 8 + tig * 2;
            if (n >= N) continue;
            if (fuse) {
                float b0 = bias[n], b1 = bias[n + 1];
                float2 v0, v1;
                v0.x = lrelu(acc[mt][nt][0] + b0);
                v0.y = lrelu(acc[mt][nt][1] + b1);
                v1.x = lrelu(acc[mt][nt][2] + b0);
                v1.y = lrelu(acc[mt][nt][3] + b1);
                *(float2*)(g_d + (size_t)m0 * N + n) = v0;
                *(float2*)(g_d + (size_t)(m0 + 8) * N + n) = v1;
            } else {
                size_t base = ((size_t)(sp * B_SZ + m0)) * N + n;
                float2 v0; v0.x = acc[mt][nt][0]; v0.y = acc[mt][nt][1];
                float2 v1; v1.x = acc[mt][nt][2]; v1.y = acc[mt][nt][3];
                *(float2*)(g_part + base) = v0;
                *(float2*)(g_part + base + (size_t)8 * N) = v1;
            }
        }
    }
}

// ---------------------------------------------------------------------------
// FC1 split-K reduction + bias + leaky -> g_z
// ---------------------------------------------------------------------------
__global__ __launch_bounds__(256) void red_k(const float* __restrict__ bias)
{
    int idx = blockIdx.x * blockDim.x + threadIdx.x;
    if (idx >= B_SZ * LATD) return;
    int m = idx / LATD, n = idx % LATD;
    float s = bias[n];
#pragma unroll
    for (int sp = 0; sp < NSPLIT1; sp++)
        s += g_part[((size_t)(sp * B_SZ + m)) * LATD + n];
    g_z[(size_t)m * LATD + n] = lrelu(s);
}

// ---------------------------------------------------------------------------
// Kernel 5: grouped conv-transpose + sigmoid
// ---------------------------------------------------------------------------
__global__ __launch_bounds__(256) void dec_conv_k(
    const float* __restrict__ w, const float* __restrict__ bias, float* __restrict__ out)
{
    int idx = blockIdx.x * blockDim.x + threadIdx.x;
    if (idx >= B_SZ * G_CNT) return;
    int b = idx / G_CNT, g = idx % G_CNT;

    const float* dp = g_d + (size_t)b * GC + (size_t)g * C_OUT;
    float d0 = dp[0], d1 = dp[1], d2 = dp[2];
    const float* wp = w + (size_t)g * (C_OUT * KWID);
    float bz = bias[g];

    float o[20];
#pragma unroll
    for (int i = 0; i < 5; i++) {
        float4 w0 = ((const float4*)(wp))[i];
        float4 w1 = ((const float4*)(wp + 20))[i];
        float4 w2 = ((const float4*)(wp + 40))[i];
        float v;
        v = fmaf(d0, w0.x, fmaf(d1, w1.x, fmaf(d2, w2.x, bz))); o[4*i+0] = v;
        v = fmaf(d0, w0.y, fmaf(d1, w1.y, fmaf(d2, w2.y, bz))); o[4*i+1] = v;
        v = fmaf(d0, w0.z, fmaf(d1, w1.z, fmaf(d2, w2.z, bz))); o[4*i+2] = v;
        v = fmaf(d0, w0.w, fmaf(d1, w1.w, fmaf(d2, w2.w, bz))); o[4*i+3] = v;
    }
    float4* op = (float4*)(out + (size_t)b * IN_LEN + g * KWID);
#pragma unroll
    for (int i = 0; i < 5; i++) {
        float4 r;
        r.x = 1.0f / (1.0f + expf(-o[4*i+0]));
        r.y = 1.0f / (1.0f + expf(-o[4*i+1]));
        r.z = 1.0f / (1.0f + expf(-o[4*i+2]));
        r.w = 1.0f / (1.0f + expf(-o[4*i+3]));
        op[i] = r;
    }
}

// ---------------------------------------------------------------------------
extern "C" void kernel_launch(void* const* d_in, const int* in_sizes, int n_in,
                              void* d_out, int out_size)
{
    const float* x        = (const float*)d_in[0];
    const float* enc_w    = (const float*)d_in[1];
    const float* enc_b    = (const float*)d_in[2];
    const float* enc_fc_w = (const float*)d_in[3];
    const float* enc_fc_b = (const float*)d_in[4];
    const float* dec_fc_w = (const float*)d_in[5];
    const float* dec_fc_b = (const float*)d_in[6];
    const float* dec_w    = (const float*)d_in[7];
    const float* dec_b    = (const float*)d_in[8];
    float* out = (float*)d_out;

    // idempotent, non-stream API (safe under graph capture)
    cudaFuncSetAttribute(fc_bf16_k, cudaFuncAttributeMaxDynamicSharedMemorySize, SMEM_BYTES);

    // 1) encoder grouped conv -> g_h
    enc_conv_k<<<(B_SZ * G_CNT + 255) / 256, 256>>>(x, enc_w, enc_b);

    // 2) FC1: [128,30000]@[2000,30000]^T. 938 BK32-steps, split 15 x 63.
    {
        dim3 grid((LATD + 127) / 128, NSPLIT1);
        fc_bf16_k<<<grid, 256, SMEM_BYTES>>>(0, enc_fc_w, nullptr, LATD, GC, 938, 63, 0);
    }
    // 3) reduce + bias + leaky -> g_z
    red_k<<<(B_SZ * LATD + 255) / 256, 256>>>(enc_fc_b);

    // 4) FC2: [128,2000]@[30000,2000]^T. 63 BK32-steps, unsplit, fused -> g_d
    {
        dim3 grid((GC + 127) / 128, 1);
        fc_bf16_k<<<grid, 256, SMEM_BYTES>>>(1, dec_fc_w, dec_fc_b, GC, LATD, 63, 63, 1);
    }

    // 5) decoder grouped conv-transpose + sigmoid -> out
    dec_conv_k<<<(B_SZ * G_CNT + 255) / 256, 256>>>(dec_w, dec_b, out);
}